// round 4
// baseline (speedup 1.0000x reference)
#include <cuda_runtime.h>
#include <cuda_pipeline.h>

#define NN    8192
#define DD    64
#define HH    4096
#define SS    4          // samples per block
#define TPS   128        // threads per sample
#define CH    32         // hidden units per thread
#define BLOCK 512
#define NB    6          // W1 ring buffers

typedef unsigned long long u64;

static __device__ __forceinline__ u64 pk(float lo, float hi) {
    u64 r; asm("mov.b64 %0,{%1,%2};" : "=l"(r) : "f"(lo), "f"(hi)); return r;
}
static __device__ __forceinline__ void upk(float& lo, float& hi, u64 v) {
    asm("mov.b64 {%0,%1},%2;" : "=f"(lo), "=f"(hi) : "l"(v));
}
static __device__ __forceinline__ u64 fma2(u64 a, u64 b, u64 c) {
    u64 d; asm("fma.rn.f32x2 %0,%1,%2,%3;" : "=l"(d) : "l"(a), "l"(b), "l"(c)); return d;
}
static __device__ __forceinline__ u64 mul2(u64 a, u64 b) {
    u64 d; asm("mul.rn.f32x2 %0,%1,%2;" : "=l"(d) : "l"(a), "l"(b)); return d;
}
static __device__ __forceinline__ u64 add2(u64 a, u64 b) {
    u64 d; asm("add.rn.f32x2 %0,%1,%2;" : "=l"(d) : "l"(a), "l"(b)); return d;
}
static __device__ __forceinline__ float frcp(float x) {
    float r; asm("rcp.approx.f32 %0,%1;" : "=f"(r) : "f"(x)); return r;
}
// accurate MUFU tanh: 2 MUFU + 3 FMA, robust at +/-inf
static __device__ __forceinline__ float ftanh(float x) {
    float e = __expf(2.0f * x);
    return 1.0f - __fdividef(2.0f, e + 1.0f);
}

#define SMEM_BYTES (NB*HH*4 + SS*DD*4 + DD*SS*4*8 + SS*2*4)

__global__ void __launch_bounds__(BLOCK, 1)
qnade_kernel(const float* __restrict__ gx,  const float* __restrict__ gW1,
             const float* __restrict__ gb1, const float* __restrict__ gW2,
             const float* __restrict__ gb2, float* __restrict__ gout)
{
    extern __shared__ char sm_[];
    float*  sW1   = (float*)sm_;                       // [NB][HH]
    float*  sX    = sW1 + NB * HH;                     // [SS][DD]
    float2* sPart = (float2*)(sX + SS * DD);           // [DD][SS][4]
    float*  sProd = (float*)(sPart + DD * SS * 4);     // [SS][2]

    const int tid  = threadIdx.x;
    const int s    = tid >> 7;
    const int wg   = tid & 127;
    const int wis  = wg >> 5;
    const int lane = tid & 31;
    const int n    = blockIdx.x * SS + s;

    // stage spins (contiguous)
    for (int i = tid; i < SS * DD; i += BLOCK)
        sX[i] = gx[blockIdx.x * SS * DD + i];

    // prefetch W1 rows 0,1 (one group)
    {
        const float4* src = (const float4*)gW1;
        float4* d0 = (float4*)(sW1 + 0 * HH);
        float4* d1 = (float4*)(sW1 + 1 * HH);
        for (int i = tid; i < HH / 4; i += BLOCK) {
            __pipeline_memcpy_async(d0 + i, src + i, 16);
            __pipeline_memcpy_async(d1 + i, src + HH / 4 + i, 16);
        }
        __pipeline_commit();
    }

    // persistent state: thread wg owns hidden units 4*wg + 512*k4 + j
    float h[CH];
    u64   w2p[CH];   // (w20,w21) pairs per owned unit
    {
        const float4* b1v = (const float4*)gb1;
        const ulonglong2* w2v = (const ulonglong2*)gW2;   // [H,2] -> pair per unit
#pragma unroll
        for (int k4 = 0; k4 < CH / 4; k4++) {
            const int f4 = wg + 128 * k4;
            float4 b = b1v[f4];
            h[k4*4+0] = b.x; h[k4*4+1] = b.y; h[k4*4+2] = b.z; h[k4*4+3] = b.w;
            ulonglong2 pa = w2v[2 * f4 + 0];
            ulonglong2 pb = w2v[2 * f4 + 1];
            w2p[k4*4+0] = pa.x; w2p[k4*4+1] = pa.y;
            w2p[k4*4+2] = pb.x; w2p[k4*4+3] = pb.y;
        }
    }
    // packed Pade[7/6] constants
    const u64 Cn378    = pk(378.0f,    378.0f);
    const u64 Cn17325  = pk(17325.0f,  17325.0f);
    const u64 C135135  = pk(135135.0f, 135135.0f);
    const u64 Cd28     = pk(28.0f,     28.0f);
    const u64 Cd3150   = pk(3150.0f,   3150.0f);
    const u64 Cd62370  = pk(62370.0f,  62370.0f);

    for (int it = 0; it < DD / 2; it++) {
        // prefetch rows 2it+2, 2it+3 into ring (always commit a group)
        {
            const int r0 = 2 * it + 2, r1 = 2 * it + 3;
            if (r1 < DD) {
                const float4* s0 = (const float4*)(gW1 + (size_t)r0 * HH);
                const float4* s1 = (const float4*)(gW1 + (size_t)r1 * HH);
                float4* d0 = (float4*)(sW1 + (r0 % NB) * HH);
                float4* d1 = (float4*)(sW1 + (r1 % NB) * HH);
                for (int i = tid; i < HH / 4; i += BLOCK) {
                    __pipeline_memcpy_async(d0 + i, s0 + i, 16);
                    __pipeline_memcpy_async(d1 + i, s1 + i, 16);
                }
            }
            __pipeline_commit();
        }
        __pipeline_wait_prior(1);   // rows 2it, 2it+1 copied (this thread)
        __syncthreads();            // ... and visible block-wide; ring-reuse safe

#pragma unroll
        for (int half = 0; half < 2; half++) {
            const int d = 2 * it + half;
            const float xd = sX[s * DD + d];
            const float4* w1v = (const float4*)(sW1 + (d % NB) * HH);
            u64 a01 = pk(0.0f, 0.0f);
#pragma unroll
            for (int k4 = 0; k4 < CH / 4; k4++) {
                float4 w = w1v[wg + 128 * k4];      // conflict-free LDS.128
                float h0 = h[k4*4+0], h1 = h[k4*4+1];
                float h2 = h[k4*4+2], h3 = h[k4*4+3];
                // rational tanh on (h0,h1), packed f32x2
                u64 x  = pk(h0, h1);
                u64 x2 = mul2(x, x);
                u64 nm = add2(x2, Cn378);
                nm = fma2(nm, x2, Cn17325);
                nm = fma2(nm, x2, C135135);
                nm = mul2(nm, x);
                u64 dn = fma2(x2, Cd28, Cd3150);
                dn = fma2(dn, x2, Cd62370);
                dn = fma2(dn, x2, C135135);
                float dl, dh; upk(dl, dh, dn);
                u64 t01 = mul2(nm, pk(frcp(dl), frcp(dh)));
                float t0, t1; upk(t0, t1, t01);
                // MUFU tanh on (h2,h3)
                float t2 = ftanh(h2);
                float t3 = ftanh(h3);
                // rank-1 update of h
                h[k4*4+0] = fmaf(xd, w.x, h0);
                h[k4*4+1] = fmaf(xd, w.y, h1);
                h[k4*4+2] = fmaf(xd, w.z, h2);
                h[k4*4+3] = fmaf(xd, w.w, h3);
                // packed dot with both W2 columns
                a01 = fma2(pk(t0, t0), w2p[k4*4+0], a01);
                a01 = fma2(pk(t1, t1), w2p[k4*4+1], a01);
                a01 = fma2(pk(t2, t2), w2p[k4*4+2], a01);
                a01 = fma2(pk(t3, t3), w2p[k4*4+3], a01);
            }
            // warp reduce (packed adds)
#pragma unroll
            for (int off = 16; off; off >>= 1) {
                u64 o = __shfl_xor_sync(0xffffffffu, a01, off);
                a01 = add2(a01, o);
            }
            if (lane == 0) {
                float A0, A1; upk(A0, A1, a01);
                sPart[(d * SS + s) * 4 + wis] = make_float2(A0, A1);
            }
        }
    }

    // deferred head: one step per thread (wg = d), then product-reduce
    __syncthreads();
    const float b20 = gb2[0], b21 = gb2[1];
    if (wg < DD) {
        const int d = wg;
        float z0 = b20, z1 = b21;
#pragma unroll
        for (int w = 0; w < 4; w++) {
            float2 v = sPart[(d * SS + s) * 4 + w];
            z0 += v.x; z1 += v.y;
        }
        float o0 = ftanh(z0), o1 = ftanh(z1);
        float nrm = fmaxf(sqrtf(o0 * o0 + o1 * o1), 1e-12f);
        float sel = (sX[s * DD + d] > 0.0f ? o0 : o1) / nrm;
#pragma unroll
        for (int off = 16; off; off >>= 1)
            sel *= __shfl_xor_sync(0xffffffffu, sel, off);
        if (lane == 0) sProd[s * 2 + wis] = sel;
    }
    __syncthreads();
    if (wg == 0) gout[n] = sProd[s * 2 + 0] * sProd[s * 2 + 1];
}

extern "C" void kernel_launch(void* const* d_in, const int* in_sizes, int n_in,
                              void* d_out, int out_size) {
    const float* x  = (const float*)d_in[0];
    const float* W1 = (const float*)d_in[1];
    const float* b1 = (const float*)d_in[2];
    const float* W2 = (const float*)d_in[3];
    const float* b2 = (const float*)d_in[4];
    cudaFuncSetAttribute(qnade_kernel,
                         cudaFuncAttributeMaxDynamicSharedMemorySize, SMEM_BYTES);
    qnade_kernel<<<NN / SS, BLOCK, SMEM_BYTES>>>(x, W1, b1, W2, b2, (float*)d_out);
}

// round 5
// speedup vs baseline: 1.1432x; 1.1432x over previous
#include <cuda_runtime.h>
#include <cuda_pipeline.h>

#define NN    8192
#define DD    64
#define HH    4096
#define SS    4          // samples per block
#define TPS   128        // threads per sample
#define CH    32         // hidden units per thread (16 pairs)
#define NP    16         // pairs per thread
#define BLOCK 512
#define NB    6          // W1 ring buffers

typedef unsigned long long u64;

static __device__ __forceinline__ u64 pk(float lo, float hi) {
    u64 r; asm("mov.b64 %0,{%1,%2};" : "=l"(r) : "f"(lo), "f"(hi)); return r;
}
static __device__ __forceinline__ void upk(float& lo, float& hi, u64 v) {
    asm("mov.b64 {%0,%1},%2;" : "=f"(lo), "=f"(hi) : "l"(v));
}
static __device__ __forceinline__ u64 fma2(u64 a, u64 b, u64 c) {
    u64 d; asm("fma.rn.f32x2 %0,%1,%2,%3;" : "=l"(d) : "l"(a), "l"(b), "l"(c)); return d;
}
static __device__ __forceinline__ u64 mul2(u64 a, u64 b) {
    u64 d; asm("mul.rn.f32x2 %0,%1,%2;" : "=l"(d) : "l"(a), "l"(b)); return d;
}
static __device__ __forceinline__ float frsq(float x) {
    float r; asm("rsqrt.approx.f32 %0,%1;" : "=f"(r) : "f"(x)); return r;
}
// accurate tanh for the tiny deferred head
static __device__ __forceinline__ float ftanh(float x) {
    float e = __expf(2.0f * x);
    return 1.0f - __fdividef(2.0f, e + 1.0f);
}

#define SMEM_BYTES (NB*HH*4 + SS*DD*4 + DD*SS*4*8 + SS*2*4)

__global__ void __launch_bounds__(BLOCK, 1)
qnade_kernel(const float* __restrict__ gx,  const float* __restrict__ gW1,
             const float* __restrict__ gb1, const float* __restrict__ gW2,
             const float* __restrict__ gb2, float* __restrict__ gout)
{
    extern __shared__ char sm_[];
    float*  sW1   = (float*)sm_;                       // [NB][HH]
    float*  sX    = sW1 + NB * HH;                     // [SS][DD]
    float2* sPart = (float2*)(sX + SS * DD);           // [DD][SS][4]
    float*  sProd = (float*)(sPart + DD * SS * 4);     // [SS][2]

    const int tid  = threadIdx.x;
    const int s    = tid >> 7;
    const int wg   = tid & 127;
    const int wis  = wg >> 5;
    const int lane = tid & 31;
    const int n    = blockIdx.x * SS + s;

    for (int i = tid; i < SS * DD; i += BLOCK)
        sX[i] = gx[blockIdx.x * SS * DD + i];

    // prefetch W1 rows 0,1
    {
        const float4* src = (const float4*)gW1;
        float4* d0 = (float4*)(sW1 + 0 * HH);
        float4* d1 = (float4*)(sW1 + 1 * HH);
        for (int i = tid; i < HH / 4; i += BLOCK) {
            __pipeline_memcpy_async(d0 + i, src + i, 16);
            __pipeline_memcpy_async(d1 + i, src + HH / 4 + i, 16);
        }
        __pipeline_commit();
    }

    // persistent packed state: thread wg owns units 4*wg + 512*k4 + j
    // pair q=2*k4+m holds units (4f4+2m, 4f4+2m+1), f4 = wg+128*k4
    u64 hp[NP], w20p[NP], w21p[NP];
    {
        const ulonglong2* b1v = (const ulonglong2*)gb1;   // float4 = 2 pairs
        const float4*     w2v = (const float4*)gW2;       // [H,2]: unit i -> (w0,w1)
#pragma unroll
        for (int k4 = 0; k4 < NP / 2; k4++) {
            const int f4 = wg + 128 * k4;
            ulonglong2 b = b1v[f4];
            hp[2*k4+0] = b.x; hp[2*k4+1] = b.y;
            float4 wa = w2v[2 * f4 + 0];   // units 4f4+0, 4f4+1
            float4 wb = w2v[2 * f4 + 1];   // units 4f4+2, 4f4+3
            w20p[2*k4+0] = pk(wa.x, wa.z); w21p[2*k4+0] = pk(wa.y, wa.w);
            w20p[2*k4+1] = pk(wb.x, wb.z); w21p[2*k4+1] = pk(wb.y, wb.w);
        }
    }
    // packed sinh Taylor coeffs 1/(2k+1)!
    const u64 C5  = pk(2.50521084e-8f, 2.50521084e-8f);
    const u64 C4  = pk(2.75573192e-6f, 2.75573192e-6f);
    const u64 C3  = pk(1.98412698e-4f, 1.98412698e-4f);
    const u64 C2  = pk(8.33333333e-3f, 8.33333333e-3f);
    const u64 C1  = pk(1.66666667e-1f, 1.66666667e-1f);
    const u64 ONE = pk(1.0f, 1.0f);

    for (int it = 0; it < DD / 2; it++) {
        {   // prefetch rows 2it+2, 2it+3 (always commit a group)
            const int r0 = 2 * it + 2, r1 = 2 * it + 3;
            if (r1 < DD) {
                const float4* s0 = (const float4*)(gW1 + (size_t)r0 * HH);
                const float4* s1 = (const float4*)(gW1 + (size_t)r1 * HH);
                float4* d0 = (float4*)(sW1 + (r0 % NB) * HH);
                float4* d1 = (float4*)(sW1 + (r1 % NB) * HH);
                for (int i = tid; i < HH / 4; i += BLOCK) {
                    __pipeline_memcpy_async(d0 + i, s0 + i, 16);
                    __pipeline_memcpy_async(d1 + i, s1 + i, 16);
                }
            }
            __pipeline_commit();
        }
        __pipeline_wait_prior(1);
        __syncthreads();

#pragma unroll
        for (int half = 0; half < 2; half++) {
            const int d = 2 * it + half;
            const float xd = sX[s * DD + d];
            const u64 xdp = pk(xd, xd);
            const ulonglong2* w1v = (const ulonglong2*)(sW1 + (d % NB) * HH);
            u64 a0p = 0ull, a1p = 0ull;   // packed (even,odd) partial dots
#pragma unroll
            for (int k4 = 0; k4 < NP / 2; k4++) {
                ulonglong2 wp = w1v[wg + 128 * k4];   // conflict-free LDS.128
#pragma unroll
                for (int m = 0; m < 2; m++) {
                    const int q = 2 * k4 + m;
                    u64 hA = hp[q];
                    // tanh(h) = s * rsqrt(1+s^2), s = h*P(h^2)
                    u64 y = mul2(hA, hA);
                    u64 p = fma2(C5, y, C4);
                    p = fma2(p, y, C3);
                    p = fma2(p, y, C2);
                    p = fma2(p, y, C1);
                    p = fma2(p, y, ONE);
                    u64 sv = mul2(p, hA);
                    u64 dd = fma2(sv, sv, ONE);
                    float dl, dh; upk(dl, dh, dd);
                    u64 t = mul2(sv, pk(frsq(dl), frsq(dh)));
                    // dots (packed even/odd lanes) + rank-1 h update
                    a0p = fma2(t, w20p[q], a0p);
                    a1p = fma2(t, w21p[q], a1p);
                    hp[q] = fma2(xdp, (m == 0) ? wp.x : wp.y, hA);
                }
            }
            // fold packed accumulators, then scalar warp reduce
            float a0l, a0h, a1l, a1h;
            upk(a0l, a0h, a0p); upk(a1l, a1h, a1p);
            float a0 = a0l + a0h, a1 = a1l + a1h;
#pragma unroll
            for (int off = 16; off; off >>= 1) {
                a0 += __shfl_xor_sync(0xffffffffu, a0, off);
                a1 += __shfl_xor_sync(0xffffffffu, a1, off);
            }
            if (lane == 0) sPart[(d * SS + s) * 4 + wis] = make_float2(a0, a1);
        }
    }

    // deferred head: one step per thread (wg = d), then product-reduce
    __syncthreads();
    const float b20 = gb2[0], b21 = gb2[1];
    if (wg < DD) {
        const int d = wg;
        float z0 = b20, z1 = b21;
#pragma unroll
        for (int w = 0; w < 4; w++) {
            float2 v = sPart[(d * SS + s) * 4 + w];
            z0 += v.x; z1 += v.y;
        }
        float o0 = ftanh(z0), o1 = ftanh(z1);
        float nrm = fmaxf(sqrtf(o0 * o0 + o1 * o1), 1e-12f);
        float sel = (sX[s * DD + d] > 0.0f ? o0 : o1) / nrm;
#pragma unroll
        for (int off = 16; off; off >>= 1)
            sel *= __shfl_xor_sync(0xffffffffu, sel, off);
        if (lane == 0) sProd[s * 2 + wis] = sel;
    }
    __syncthreads();
    if (wg == 0) gout[n] = sProd[s * 2 + 0] * sProd[s * 2 + 1];
}

extern "C" void kernel_launch(void* const* d_in, const int* in_sizes, int n_in,
                              void* d_out, int out_size) {
    const float* x  = (const float*)d_in[0];
    const float* W1 = (const float*)d_in[1];
    const float* b1 = (const float*)d_in[2];
    const float* W2 = (const float*)d_in[3];
    const float* b2 = (const float*)d_in[4];
    cudaFuncSetAttribute(qnade_kernel,
                         cudaFuncAttributeMaxDynamicSharedMemorySize, SMEM_BYTES);
    qnade_kernel<<<NN / SS, BLOCK, SMEM_BYTES>>>(x, W1, b1, W2, b2, (float*)d_out);
}

// round 7
// speedup vs baseline: 1.1637x; 1.0179x over previous
#include <cuda_runtime.h>
#include <cuda_pipeline.h>

#define NN    8192
#define DD    64
#define HH    4096
#define SS    4          // samples per block
#define TPS   128        // threads per sample
#define CH    32         // hidden units per thread (16 pairs)
#define NP    16         // pairs per thread
#define BLOCK 512
#define NB    8          // W1 ring rows (4-row groups, sync every 4 steps)

typedef unsigned long long u64;

static __device__ __forceinline__ u64 pk(float lo, float hi) {
    u64 r; asm("mov.b64 %0,{%1,%2};" : "=l"(r) : "f"(lo), "f"(hi)); return r;
}
static __device__ __forceinline__ void upk(float& lo, float& hi, u64 v) {
    asm("mov.b64 {%0,%1},%2;" : "=f"(lo), "=f"(hi) : "l"(v));
}
static __device__ __forceinline__ u64 fma2(u64 a, u64 b, u64 c) {
    u64 d; asm("fma.rn.f32x2 %0,%1,%2,%3;" : "=l"(d) : "l"(a), "l"(b), "l"(c)); return d;
}
static __device__ __forceinline__ u64 mul2(u64 a, u64 b) {
    u64 d; asm("mul.rn.f32x2 %0,%1,%2;" : "=l"(d) : "l"(a), "l"(b)); return d;
}
static __device__ __forceinline__ float frsq(float x) {
    float r; asm("rsqrt.approx.f32 %0,%1;" : "=f"(r) : "f"(x)); return r;
}
static __device__ __forceinline__ float frcp(float x) {
    float r; asm("rcp.approx.f32 %0,%1;" : "=f"(r) : "f"(x)); return r;
}
static __device__ __forceinline__ float fex2(float x) {
    float r; asm("ex2.approx.f32 %0,%1;" : "=f"(r) : "f"(x)); return r;
}
// accurate tanh for the tiny deferred head
static __device__ __forceinline__ float ftanh(float x) {
    float e = __expf(2.0f * x);
    return 1.0f - __fdividef(2.0f, e + 1.0f);
}
// MUFU-path packed tanh: t = 1 - 2/(1 + e^{2x}); robust at +/-inf.
static __device__ __forceinline__ u64 tanh2_ex2(u64 hA) {
    float h0, h1; upk(h0, h1, hA);
    float e0 = fex2(h0 * 2.8853901817f);     // 2*log2(e)
    float e1 = fex2(h1 * 2.8853901817f);
    float t0 = fmaf(-2.0f, frcp(e0 + 1.0f), 1.0f);
    float t1 = fmaf(-2.0f, frcp(e1 + 1.0f), 1.0f);
    return pk(t0, t1);
}

#define SMEM_BYTES (NB*HH*4 + SS*DD*4 + DD*SS*4*8 + SS*2*4)

__global__ void __launch_bounds__(BLOCK, 1)
qnade_kernel(const float* __restrict__ gx,  const float* __restrict__ gW1,
             const float* __restrict__ gb1, const float* __restrict__ gW2,
             const float* __restrict__ gb2, float* __restrict__ gout)
{
    extern __shared__ char sm_[];
    float*  sW1   = (float*)sm_;                       // [NB][HH] ring
    float*  sX    = sW1 + NB * HH;                     // [SS][DD]
    float2* sPart = (float2*)(sX + SS * DD);           // [DD][SS][4]
    float*  sProd = (float*)(sPart + DD * SS * 4);     // [SS][2]

    const int tid  = threadIdx.x;
    const int s    = tid >> 7;
    const int wg   = tid & 127;
    const int wis  = wg >> 5;
    const int lane = tid & 31;
    const int n    = blockIdx.x * SS + s;

    for (int i = tid; i < SS * DD; i += BLOCK)
        sX[i] = gx[blockIdx.x * SS * DD + i];

    // prefetch W1 rows 0..3 as one group
    {
        const float4* src = (const float4*)gW1;
#pragma unroll
        for (int r = 0; r < 4; r++) {
            float4* dst = (float4*)(sW1 + r * HH);
            for (int i = tid; i < HH / 4; i += BLOCK)
                __pipeline_memcpy_async(dst + i, src + r * (HH / 4) + i, 16);
        }
        __pipeline_commit();
    }

    // persistent packed state: thread wg owns units 4*wg + 512*k4 + j
    u64 hp[NP], w20p[NP], w21p[NP];
    {
        const ulonglong2* b1v = (const ulonglong2*)gb1;
        const float4*     w2v = (const float4*)gW2;       // [H,2]
#pragma unroll
        for (int k4 = 0; k4 < NP / 2; k4++) {
            const int f4 = wg + 128 * k4;
            ulonglong2 b = b1v[f4];
            hp[2*k4+0] = b.x; hp[2*k4+1] = b.y;
            float4 wa = w2v[2 * f4 + 0];
            float4 wb = w2v[2 * f4 + 1];
            w20p[2*k4+0] = pk(wa.x, wa.z); w21p[2*k4+0] = pk(wa.y, wa.w);
            w20p[2*k4+1] = pk(wb.x, wb.z); w21p[2*k4+1] = pk(wb.y, wb.w);
        }
    }
    // packed sinh Taylor coeffs (deg-4: through x^9)
    const u64 C4  = pk(2.75573192e-6f, 2.75573192e-6f);
    const u64 C3  = pk(1.98412698e-4f, 1.98412698e-4f);
    const u64 C2  = pk(8.33333333e-3f, 8.33333333e-3f);
    const u64 C1  = pk(1.66666667e-1f, 1.66666667e-1f);
    const u64 ONE = pk(1.0f, 1.0f);

    for (int it = 0; it < DD / 4; it++) {
        // 1) all prior copies (incl. group `it`, rows 4it..4it+3) done locally
        __pipeline_wait_prior(0);
        // 2) block-wide: copies visible AND all reads of the slots we're about
        //    to overwrite (iteration it-1's rows) have completed
        __syncthreads();
        // 3) issue prefetch of rows 4it+4..4it+7 into slots (4it+4..7)%NB —
        //    disjoint from this iteration's read slots (4it..4it+3)%NB
        {
#pragma unroll
            for (int r = 0; r < 4; r++) {
                const int row = 4 * it + 4 + r;
                if (row < DD) {
                    const float4* src = (const float4*)(gW1 + (size_t)row * HH);
                    float4* dst = (float4*)(sW1 + (row % NB) * HH);
                    for (int i = tid; i < HH / 4; i += BLOCK)
                        __pipeline_memcpy_async(dst + i, src + i, 16);
                }
            }
            __pipeline_commit();
        }

        // 4) compute 4 steps on rows 4it..4it+3 (copy of next group overlaps)
#pragma unroll
        for (int h4 = 0; h4 < 4; h4++) {
            const int d = 4 * it + h4;
            const float xd = sX[s * DD + d];
            const u64 xdp = pk(xd, xd);
            const ulonglong2* w1v = (const ulonglong2*)(sW1 + (d % NB) * HH);
            u64 a0p = 0ull, a1p = 0ull;
#pragma unroll
            for (int k4 = 0; k4 < NP / 2; k4++) {
                ulonglong2 wp = w1v[wg + 128 * k4];   // conflict-free LDS.128
#pragma unroll
                for (int m = 0; m < 2; m++) {
                    const int q = 2 * k4 + m;
                    u64 hA = hp[q];
                    u64 t;
                    if ((q & 3) == 0) {
                        // MUFU path on 4 of 16 pairs (pipe balancing)
                        t = tanh2_ex2(hA);
                    } else {
                        // FMA path: tanh = s*rsqrt(1+s^2), s = h*P(h^2), deg-4
                        u64 y = mul2(hA, hA);
                        u64 p = fma2(C4, y, C3);
                        p = fma2(p, y, C2);
                        p = fma2(p, y, C1);
                        p = fma2(p, y, ONE);
                        u64 sv = mul2(p, hA);
                        u64 dd2 = fma2(sv, sv, ONE);
                        float dl, dh; upk(dl, dh, dd2);
                        t = mul2(sv, pk(frsq(dl), frsq(dh)));
                    }
                    a0p = fma2(t, w20p[q], a0p);
                    a1p = fma2(t, w21p[q], a1p);
                    hp[q] = fma2(xdp, (m == 0) ? wp.x : wp.y, hA);
                }
            }
            float a0l, a0h, a1l, a1h;
            upk(a0l, a0h, a0p); upk(a1l, a1h, a1p);
            float a0 = a0l + a0h, a1 = a1l + a1h;
#pragma unroll
            for (int off = 16; off; off >>= 1) {
                a0 += __shfl_xor_sync(0xffffffffu, a0, off);
                a1 += __shfl_xor_sync(0xffffffffu, a1, off);
            }
            if (lane == 0) sPart[(d * SS + s) * 4 + wis] = make_float2(a0, a1);
        }
    }

    // deferred head: one step per thread (wg = d), then product-reduce
    __syncthreads();
    const float b20 = gb2[0], b21 = gb2[1];
    if (wg < DD) {
        const int d = wg;
        float z0 = b20, z1 = b21;
#pragma unroll
        for (int w = 0; w < 4; w++) {
            float2 v = sPart[(d * SS + s) * 4 + w];
            z0 += v.x; z1 += v.y;
        }
        float o0 = ftanh(z0), o1 = ftanh(z1);
        float nrm = fmaxf(sqrtf(o0 * o0 + o1 * o1), 1e-12f);
        float sel = (sX[s * DD + d] > 0.0f ? o0 : o1) / nrm;
#pragma unroll
        for (int off = 16; off; off >>= 1)
            sel *= __shfl_xor_sync(0xffffffffu, sel, off);
        if (lane == 0) sProd[s * 2 + wis] = sel;
    }
    __syncthreads();
    if (wg == 0) gout[n] = sProd[s * 2 + 0] * sProd[s * 2 + 1];
}

extern "C" void kernel_launch(void* const* d_in, const int* in_sizes, int n_in,
                              void* d_out, int out_size) {
    const float* x  = (const float*)d_in[0];
    const float* W1 = (const float*)d_in[1];
    const float* b1 = (const float*)d_in[2];
    const float* W2 = (const float*)d_in[3];
    const float* b2 = (const float*)d_in[4];
    cudaFuncSetAttribute(qnade_kernel,
                         cudaFuncAttributeMaxDynamicSharedMemorySize, SMEM_BYTES);
    qnade_kernel<<<NN / SS, BLOCK, SMEM_BYTES>>>(x, W1, b1, W2, b2, (float*)d_out);
}